// round 1
// baseline (speedup 1.0000x reference)
#include <cuda_runtime.h>

#define G     8
#define DD    8
#define CIN   64
#define COUT  64
#define KS    7
#define PAD   3
#define H     56
#define W     56
#define B     4
#define HP    62   // padded
#define WP    62

#define TH     8             // rows per attention block
#define TROWS  (TH + KS - 1) // 14

// scratch (allocation-free rule: __device__ globals)
__device__ float g_q[B*COUT*H*W];
__device__ float g_k[B*COUT*HP*WP];
__device__ float g_v[B*COUT*HP*WP];

// ---------------------------------------------------------------------------
// Kernel 1: fused grouped 1x1 conv for q (interior) and k/v (padded grid)
// ---------------------------------------------------------------------------
__global__ void qkv_kernel(const float* __restrict__ x,
                           const float* __restrict__ wq,
                           const float* __restrict__ wk,
                           const float* __restrict__ bk,
                           const float* __restrict__ wv,
                           const float* __restrict__ bv) {
    int idx = blockIdx.x * blockDim.x + threadIdx.x;
    if (idx >= B*COUT*HP*WP) return;
    int xw = idx % WP;
    int t  = idx / WP;
    int yh = t % HP;  t /= HP;
    int c  = t % COUT;
    int b  = t / COUT;
    int g  = c >> 3;

    float acck = bk[c];
    float accv = bv[c];
    int hy = yh - PAD, wx = xw - PAD;
    if (hy >= 0 && hy < H && wx >= 0 && wx < W) {
        const float* xp = x + (((b*CIN) + g*8)*H + hy)*W + wx;
        float accq = 0.f;
        #pragma unroll
        for (int i = 0; i < 8; i++) {
            float xv = xp[i*H*W];
            accq = fmaf(wq[c*8 + i], xv, accq);
            acck = fmaf(wk[c*8 + i], xv, acck);
            accv = fmaf(wv[c*8 + i], xv, accv);
        }
        g_q[((b*COUT + c)*H + hy)*W + wx] = accq;
    }
    g_k[idx] = acck;
    g_v[idx] = accv;
}

// ---------------------------------------------------------------------------
// Kernel 2: windowed softmax attention.
// Block = (b, c, 8-row tile). 224 threads, each owns positions (h, 2w) & (h, 2w+1).
// logits[n] = q * (k[n] + r[d,n]); softmax over 49; weighted sum with v.
// exp computed as ex2.approx with log2e folded into q (no max-sub needed:
// softmax is shift-invariant and |logits| is small here).
// ---------------------------------------------------------------------------
__global__ __launch_bounds__(224)
void attn_kernel(const float* __restrict__ rel_x,
                 const float* __restrict__ rel_y,
                 float* __restrict__ out) {
    __shared__ float ks_[TROWS*WP];
    __shared__ float vs_[TROWS*WP];
    __shared__ float rsh[KS*KS];

    int ht = blockIdx.x;   // 0..6
    int c  = blockIdx.y;   // 0..63
    int b  = blockIdx.z;   // 0..3
    int h0 = ht * TH;
    int tid = threadIdx.x;

    // stage k/v tile: padded rows [h0, h0+14), all 62 cols (contiguous)
    int base = ((b*COUT + c)*HP + h0)*WP;
    for (int i = tid; i < TROWS*WP; i += 224) {
        ks_[i] = g_k[base + i];
        vs_[i] = g_v[base + i];
    }
    // relative-position table for this channel's d
    int d = c & 7;
    if (tid < KS*KS) {
        int jy = tid / KS, jx = tid % KS;
        rsh[tid] = (d < 4) ? rel_x[d*KS + jy] : rel_y[(d - 4)*KS + jx];
    }
    __syncthreads();

    int hl = tid / 28;          // 0..7 local row
    int wp = tid % 28;          // 0..27 pair index
    int h  = h0 + hl;
    int w0 = wp * 2;

    const float LOG2E = 1.4426950408889634f;
    int qi = ((b*COUT + c)*H + h)*W + w0;
    float q0 = g_q[qi]     * LOG2E;
    float q1 = g_q[qi + 1] * LOG2E;

    float s0 = 0.f, s1 = 0.f, o0 = 0.f, o1 = 0.f;
    #pragma unroll
    for (int jy = 0; jy < KS; jy++) {
        int rb = (hl + jy)*WP + w0;
        #pragma unroll
        for (int jx = 0; jx < KS; jx++) {
            float rr = rsh[jy*KS + jx];
            float k0 = ks_[rb + jx];
            float k1 = ks_[rb + jx + 1];
            float l0 = q0 * (k0 + rr);
            float l1 = q1 * (k1 + rr);
            float e0, e1;
            asm("ex2.approx.ftz.f32 %0, %1;" : "=f"(e0) : "f"(l0));
            asm("ex2.approx.ftz.f32 %0, %1;" : "=f"(e1) : "f"(l1));
            s0 += e0;
            s1 += e1;
            o0 = fmaf(e0, vs_[rb + jx],     o0);
            o1 = fmaf(e1, vs_[rb + jx + 1], o1);
        }
    }

    float r0 = __fdividef(o0, s0);
    float r1 = __fdividef(o1, s1);
    out[qi]     = r0;
    out[qi + 1] = r1;
}

// ---------------------------------------------------------------------------
extern "C" void kernel_launch(void* const* d_in, const int* in_sizes, int n_in,
                              void* d_out, int out_size) {
    const float* x     = (const float*)d_in[0];
    const float* wq    = (const float*)d_in[1];
    const float* wk    = (const float*)d_in[2];
    const float* bk    = (const float*)d_in[3];
    const float* wv    = (const float*)d_in[4];
    const float* bv    = (const float*)d_in[5];
    const float* rel_x = (const float*)d_in[6];
    const float* rel_y = (const float*)d_in[7];
    float* out = (float*)d_out;

    int n1 = B*COUT*HP*WP;
    qkv_kernel<<<(n1 + 255)/256, 256>>>(x, wq, wk, bk, wv, bv);

    dim3 grid(H/TH, COUT, B);   // (7, 64, 4)
    attn_kernel<<<grid, 224>>>(rel_x, rel_y, out);
}

// round 2
// speedup vs baseline: 1.0960x; 1.0960x over previous
#include <cuda_runtime.h>

#define G     8
#define DD    8
#define CIN   64
#define COUT  64
#define KS    7
#define PAD   3
#define H     56
#define W     56
#define B     4

#define TH    16            // output rows per attn block (last block: 8)
#define TRW   (TH + KS - 1) // 22 staged rows
#define SP    68            // padded shared row stride (floats): breaks 128B row aliasing

// scratch (allocation-free rule: __device__ globals), all interior 56x56 layout
__device__ float g_q[B*COUT*H*W];
__device__ float g_k[B*COUT*H*W];
__device__ float g_v[B*COUT*H*W];

// ---------------------------------------------------------------------------
// Kernel 1: fused grouped 1x1 conv. 4 outputs per thread (float4), interior
// grid only (attn fills the halo with the bias). log2(e) folded into wq.
// ---------------------------------------------------------------------------
__global__ __launch_bounds__(256)
void qkv_kernel(const float* __restrict__ x,
                const float* __restrict__ wq,
                const float* __restrict__ wk,
                const float* __restrict__ bk,
                const float* __restrict__ wv,
                const float* __restrict__ bv) {
    const float LOG2E = 1.4426950408889634f;
    int idx = blockIdx.x * 256 + threadIdx.x;          // 200,704 threads exactly
    int j = idx % 14;
    int t = idx / 14;
    int h = t % 56;  t /= 56;
    int c = t % 64;
    int b = t / 64;
    int g = c >> 3;

    const float4* xp = (const float4*)x + ((b*CIN + g*8)*H + h)*14 + j;

    float kb = __ldg(&bk[c]);
    float vb = __ldg(&bv[c]);
    float4 aq = make_float4(0.f, 0.f, 0.f, 0.f);
    float4 ak = make_float4(kb, kb, kb, kb);
    float4 av = make_float4(vb, vb, vb, vb);

    #pragma unroll
    for (int i = 0; i < 8; i++) {
        float4 xv  = __ldg(xp + i*784);                 // 784 = H*W/4
        float wqi  = __ldg(&wq[c*8 + i]) * LOG2E;
        float wki  = __ldg(&wk[c*8 + i]);
        float wvi  = __ldg(&wv[c*8 + i]);
        aq.x = fmaf(wqi, xv.x, aq.x); aq.y = fmaf(wqi, xv.y, aq.y);
        aq.z = fmaf(wqi, xv.z, aq.z); aq.w = fmaf(wqi, xv.w, aq.w);
        ak.x = fmaf(wki, xv.x, ak.x); ak.y = fmaf(wki, xv.y, ak.y);
        ak.z = fmaf(wki, xv.z, ak.z); ak.w = fmaf(wki, xv.w, ak.w);
        av.x = fmaf(wvi, xv.x, av.x); av.y = fmaf(wvi, xv.y, av.y);
        av.z = fmaf(wvi, xv.z, av.z); av.w = fmaf(wvi, xv.w, av.w);
    }
    ((float4*)g_q)[idx] = aq;
    ((float4*)g_k)[idx] = ak;
    ((float4*)g_v)[idx] = av;
}

// ---------------------------------------------------------------------------
// Kernel 2: windowed softmax attention, 4 consecutive outputs per thread.
// Block = (row16-tile, c, b), 224 threads = 16 rows x 14 col-quads.
// rel table is rank-1: d<4 -> const over jx (hoist per jy); d>=4 -> const
// over jy (hoist per thread). logits via single FFMA per tap, exp via
// ex2.approx (log2e prefolded in qkv).
// ---------------------------------------------------------------------------
#define EX2F(dst, src) asm("ex2.approx.ftz.f32 %0, %1;" : "=f"(dst) : "f"(src))

__global__ __launch_bounds__(224)
void attn_kernel(const float* __restrict__ rel_x,
                 const float* __restrict__ rel_y,
                 const float* __restrict__ bk,
                 const float* __restrict__ bv,
                 float* __restrict__ out) {
    __shared__ float ks_[TRW*SP];
    __shared__ float vs_[TRW*SP];

    int ht = blockIdx.x;   // 0..3 (row tile)
    int c  = blockIdx.y;   // 0..63
    int b  = blockIdx.z;   // 0..3
    int h0 = ht * TH;
    int tid = threadIdx.x;
    int d = c & 7;

    float kb = __ldg(&bk[c]);
    float vb = __ldg(&bv[c]);

    // stage padded 22x62 tile from interior-grid k/v, halo = bias
    int cbase = (b*COUT + c)*H;
    for (int i = tid; i < TRW*64; i += 224) {
        int pr = i >> 6, pc = i & 63;
        int hy = h0 + pr - PAD, wx = pc - PAD;
        bool in = ((unsigned)hy < (unsigned)H) && ((unsigned)wx < (unsigned)W);
        int gi = (cbase + hy)*W + wx;
        int si = pr*SP + pc;
        ks_[si] = in ? g_k[gi] : kb;
        vs_[si] = in ? g_v[gi] : vb;
    }
    __syncthreads();

    int r  = tid / 14;
    int qd = tid - r*14;
    int h  = h0 + r;
    if (h >= H) return;
    int w0 = qd * 4;

    // q (already scaled by log2e)
    float4 qv = ((const float4*)g_q)[(cbase + h)*14 + qd];
    float q0 = qv.x, q1 = qv.y, q2 = qv.z, q3 = qv.w;

    float relv[7];
    #pragma unroll
    for (int jj = 0; jj < 7; jj++)
        relv[jj] = (d < 4) ? __ldg(&rel_x[d*KS + jj]) : __ldg(&rel_y[(d-4)*KS + jj]);

    float s0 = 0.f, s1 = 0.f, s2 = 0.f, s3 = 0.f;
    float o0 = 0.f, o1 = 0.f, o2 = 0.f, o3 = 0.f;

    if (d < 4) {
        // rel constant over jx: hoist qr per jy
        #pragma unroll
        for (int jy = 0; jy < KS; jy++) {
            int rb = (r + jy)*SP + w0;
            float4 k4a = *(const float4*)(ks_ + rb);
            float4 k4b = *(const float4*)(ks_ + rb + 4);
            float2 k2c = *(const float2*)(ks_ + rb + 8);
            float4 v4a = *(const float4*)(vs_ + rb);
            float4 v4b = *(const float4*)(vs_ + rb + 4);
            float2 v2c = *(const float2*)(vs_ + rb + 8);
            float kk[10] = {k4a.x,k4a.y,k4a.z,k4a.w,k4b.x,k4b.y,k4b.z,k4b.w,k2c.x,k2c.y};
            float vv[10] = {v4a.x,v4a.y,v4a.z,v4a.w,v4b.x,v4b.y,v4b.z,v4b.w,v2c.x,v2c.y};
            float rj = relv[jy];
            float a0 = q0*rj, a1 = q1*rj, a2 = q2*rj, a3 = q3*rj;
            #pragma unroll
            for (int jx = 0; jx < KS; jx++) {
                float e0, e1, e2, e3;
                EX2F(e0, fmaf(q0, kk[jx],   a0));
                EX2F(e1, fmaf(q1, kk[jx+1], a1));
                EX2F(e2, fmaf(q2, kk[jx+2], a2));
                EX2F(e3, fmaf(q3, kk[jx+3], a3));
                s0 += e0; s1 += e1; s2 += e2; s3 += e3;
                o0 = fmaf(e0, vv[jx],   o0);
                o1 = fmaf(e1, vv[jx+1], o1);
                o2 = fmaf(e2, vv[jx+2], o2);
                o3 = fmaf(e3, vv[jx+3], o3);
            }
        }
    } else {
        // rel constant over jy: hoist qr per thread
        float a0[7], a1[7], a2[7], a3[7];
        #pragma unroll
        for (int jx = 0; jx < KS; jx++) {
            a0[jx] = q0*relv[jx]; a1[jx] = q1*relv[jx];
            a2[jx] = q2*relv[jx]; a3[jx] = q3*relv[jx];
        }
        #pragma unroll
        for (int jy = 0; jy < KS; jy++) {
            int rb = (r + jy)*SP + w0;
            float4 k4a = *(const float4*)(ks_ + rb);
            float4 k4b = *(const float4*)(ks_ + rb + 4);
            float2 k2c = *(const float2*)(ks_ + rb + 8);
            float4 v4a = *(const float4*)(vs_ + rb);
            float4 v4b = *(const float4*)(vs_ + rb + 4);
            float2 v2c = *(const float2*)(vs_ + rb + 8);
            float kk[10] = {k4a.x,k4a.y,k4a.z,k4a.w,k4b.x,k4b.y,k4b.z,k4b.w,k2c.x,k2c.y};
            float vv[10] = {v4a.x,v4a.y,v4a.z,v4a.w,v4b.x,v4b.y,v4b.z,v4b.w,v2c.x,v2c.y};
            #pragma unroll
            for (int jx = 0; jx < KS; jx++) {
                float e0, e1, e2, e3;
                EX2F(e0, fmaf(q0, kk[jx],   a0[jx]));
                EX2F(e1, fmaf(q1, kk[jx+1], a1[jx]));
                EX2F(e2, fmaf(q2, kk[jx+2], a2[jx]));
                EX2F(e3, fmaf(q3, kk[jx+3], a3[jx]));
                s0 += e0; s1 += e1; s2 += e2; s3 += e3;
                o0 = fmaf(e0, vv[jx],   o0);
                o1 = fmaf(e1, vv[jx+1], o1);
                o2 = fmaf(e2, vv[jx+2], o2);
                o3 = fmaf(e3, vv[jx+3], o3);
            }
        }
    }

    float4 res;
    res.x = __fdividef(o0, s0);
    res.y = __fdividef(o1, s1);
    res.z = __fdividef(o2, s2);
    res.w = __fdividef(o3, s3);
    *(float4*)&out[(cbase + h)*W + w0] = res;
}

// ---------------------------------------------------------------------------
extern "C" void kernel_launch(void* const* d_in, const int* in_sizes, int n_in,
                              void* d_out, int out_size) {
    const float* x     = (const float*)d_in[0];
    const float* wq    = (const float*)d_in[1];
    const float* wk    = (const float*)d_in[2];
    const float* bk    = (const float*)d_in[3];
    const float* wv    = (const float*)d_in[4];
    const float* bv    = (const float*)d_in[5];
    const float* rel_x = (const float*)d_in[6];
    const float* rel_y = (const float*)d_in[7];
    float* out = (float*)d_out;

    qkv_kernel<<<784, 256>>>(x, wq, wk, bk, wv, bv);   // 200,704 threads exact

    dim3 grid(4, COUT, B);   // (4, 64, 4) = 1024 blocks
    attn_kernel<<<grid, 224>>>(rel_x, rel_y, bk, bv, out);
}

// round 3
// speedup vs baseline: 1.1217x; 1.0234x over previous
#include <cuda_runtime.h>

#define G     8
#define DD    8
#define CIN   64
#define COUT  64
#define KS    7
#define PAD   3
#define H     56
#define W     56
#define B     4

#define TH    8             // output rows per attn block
#define TRW   (TH + KS - 1) // 14 staged rows
#define SP    66            // shared row stride (floats), even (float2) + bank stagger

// scratch (allocation-free rule: __device__ globals), interior 56x56 layout
__device__ float g_q[B*COUT*H*W];
__device__ float g_k[B*COUT*H*W];
__device__ float g_v[B*COUT*H*W];

// ---------------------------------------------------------------------------
// Kernel 1: fused grouped 1x1 conv, 4 outputs/thread (float4), interior grid.
// log2(e) folded into wq.
// ---------------------------------------------------------------------------
__global__ __launch_bounds__(256)
void qkv_kernel(const float* __restrict__ x,
                const float* __restrict__ wq,
                const float* __restrict__ wk,
                const float* __restrict__ bk,
                const float* __restrict__ wv,
                const float* __restrict__ bv) {
    const float LOG2E = 1.4426950408889634f;
    int idx = blockIdx.x * 256 + threadIdx.x;          // 200,704 threads exact
    int j = idx % 14;
    int t = idx / 14;
    int h = t % 56;  t /= 56;
    int c = t % 64;
    int b = t / 64;
    int g = c >> 3;

    const float4* xp = (const float4*)x + ((b*CIN + g*8)*H + h)*14 + j;

    float kb = __ldg(&bk[c]);
    float vb = __ldg(&bv[c]);
    float4 aq = make_float4(0.f, 0.f, 0.f, 0.f);
    float4 ak = make_float4(kb, kb, kb, kb);
    float4 av = make_float4(vb, vb, vb, vb);

    #pragma unroll
    for (int i = 0; i < 8; i++) {
        float4 xv  = __ldg(xp + i*784);                 // 784 = H*W/4
        float wqi  = __ldg(&wq[c*8 + i]) * LOG2E;
        float wki  = __ldg(&wk[c*8 + i]);
        float wvi  = __ldg(&wv[c*8 + i]);
        aq.x = fmaf(wqi, xv.x, aq.x); aq.y = fmaf(wqi, xv.y, aq.y);
        aq.z = fmaf(wqi, xv.z, aq.z); aq.w = fmaf(wqi, xv.w, aq.w);
        ak.x = fmaf(wki, xv.x, ak.x); ak.y = fmaf(wki, xv.y, ak.y);
        ak.z = fmaf(wki, xv.z, ak.z); ak.w = fmaf(wki, xv.w, ak.w);
        av.x = fmaf(wvi, xv.x, av.x); av.y = fmaf(wvi, xv.y, av.y);
        av.z = fmaf(wvi, xv.z, av.z); av.w = fmaf(wvi, xv.w, av.w);
    }
    ((float4*)g_q)[idx] = aq;
    ((float4*)g_k)[idx] = ak;
    ((float4*)g_v)[idx] = av;
}

// ---------------------------------------------------------------------------
// Kernel 2: windowed softmax attention, 2 adjacent outputs per thread.
// Block = (row8-tile, c, b), 224 threads = 8 rows x 28 col-pairs. Grid 1792.
// rel is rank-1: d<4 const over jx (hoist per jy), d>=4 const over jy
// (hoist per thread). logits = fma(q, k, q*rel); exp = bare ex2.approx.
// ---------------------------------------------------------------------------
#define EX2F(dst, src) asm("ex2.approx.ftz.f32 %0, %1;" : "=f"(dst) : "f"(src))

__global__ __launch_bounds__(224)
void attn_kernel(const float* __restrict__ rel_x,
                 const float* __restrict__ rel_y,
                 const float* __restrict__ bk,
                 const float* __restrict__ bv,
                 float* __restrict__ out) {
    __shared__ float ks_[TRW*SP];
    __shared__ float vs_[TRW*SP];

    int ht = blockIdx.x;   // 0..6
    int c  = blockIdx.y;   // 0..63
    int b  = blockIdx.z;   // 0..3
    int h0 = ht * TH;
    int tid = threadIdx.x;
    int d = c & 7;

    float kb = __ldg(&bk[c]);
    float vb = __ldg(&bv[c]);

    // stage padded 14x62 tile from interior-grid k/v; halo = bias
    int cbase = (b*COUT + c)*H;
    for (int i = tid; i < TRW*64; i += 224) {
        int pr = i >> 6, pc = i & 63;
        int hy = h0 + pr - PAD, wx = pc - PAD;
        bool in = ((unsigned)hy < (unsigned)H) && ((unsigned)wx < (unsigned)W);
        int gi = (cbase + hy)*W + wx;
        int si = pr*SP + pc;
        ks_[si] = in ? g_k[gi] : kb;
        vs_[si] = in ? g_v[gi] : vb;
    }
    __syncthreads();

    int r  = tid / 28;          // local row 0..7
    int wp = tid - r*28;        // col pair 0..27
    int h  = h0 + r;
    int w0 = wp * 2;

    float2 qv = ((const float2*)g_q)[(cbase + h)*28 + wp];  // pre-scaled by log2e
    float q0 = qv.x, q1 = qv.y;

    float relv[7];
    #pragma unroll
    for (int jj = 0; jj < 7; jj++)
        relv[jj] = (d < 4) ? __ldg(&rel_x[d*KS + jj]) : __ldg(&rel_y[(d-4)*KS + jj]);

    float s0 = 0.f, s1 = 0.f, o0 = 0.f, o1 = 0.f;

    if (d < 4) {
        #pragma unroll
        for (int jy = 0; jy < KS; jy++) {
            int rb = (r + jy)*SP + w0;
            float2 ka = *(const float2*)(ks_ + rb);
            float2 kbv = *(const float2*)(ks_ + rb + 2);
            float2 kc = *(const float2*)(ks_ + rb + 4);
            float2 kd = *(const float2*)(ks_ + rb + 6);
            float2 va = *(const float2*)(vs_ + rb);
            float2 vb2 = *(const float2*)(vs_ + rb + 2);
            float2 vc = *(const float2*)(vs_ + rb + 4);
            float2 vd = *(const float2*)(vs_ + rb + 6);
            float kk[8] = {ka.x,ka.y,kbv.x,kbv.y,kc.x,kc.y,kd.x,kd.y};
            float vv[8] = {va.x,va.y,vb2.x,vb2.y,vc.x,vc.y,vd.x,vd.y};
            float a0 = q0 * relv[jy];
            float a1 = q1 * relv[jy];
            #pragma unroll
            for (int jx = 0; jx < KS; jx++) {
                float e0, e1;
                EX2F(e0, fmaf(q0, kk[jx],   a0));
                EX2F(e1, fmaf(q1, kk[jx+1], a1));
                s0 += e0; s1 += e1;
                o0 = fmaf(e0, vv[jx],   o0);
                o1 = fmaf(e1, vv[jx+1], o1);
            }
        }
    } else {
        float a0[7], a1[7];
        #pragma unroll
        for (int jx = 0; jx < KS; jx++) {
            a0[jx] = q0 * relv[jx];
            a1[jx] = q1 * relv[jx];
        }
        #pragma unroll
        for (int jy = 0; jy < KS; jy++) {
            int rb = (r + jy)*SP + w0;
            float2 ka = *(const float2*)(ks_ + rb);
            float2 kbv = *(const float2*)(ks_ + rb + 2);
            float2 kc = *(const float2*)(ks_ + rb + 4);
            float2 kd = *(const float2*)(ks_ + rb + 6);
            float2 va = *(const float2*)(vs_ + rb);
            float2 vb2 = *(const float2*)(vs_ + rb + 2);
            float2 vc = *(const float2*)(vs_ + rb + 4);
            float2 vd = *(const float2*)(vs_ + rb + 6);
            float kk[8] = {ka.x,ka.y,kbv.x,kbv.y,kc.x,kc.y,kd.x,kd.y};
            float vv[8] = {va.x,va.y,vb2.x,vb2.y,vc.x,vc.y,vd.x,vd.y};
            #pragma unroll
            for (int jx = 0; jx < KS; jx++) {
                float e0, e1;
                EX2F(e0, fmaf(q0, kk[jx],   a0[jx]));
                EX2F(e1, fmaf(q1, kk[jx+1], a1[jx]));
                s0 += e0; s1 += e1;
                o0 = fmaf(e0, vv[jx],   o0);
                o1 = fmaf(e1, vv[jx+1], o1);
            }
        }
    }

    float2 res;
    res.x = __fdividef(o0, s0);
    res.y = __fdividef(o1, s1);
    *(float2*)&out[(cbase + h)*W + w0] = res;
}

// ---------------------------------------------------------------------------
extern "C" void kernel_launch(void* const* d_in, const int* in_sizes, int n_in,
                              void* d_out, int out_size) {
    const float* x     = (const float*)d_in[0];
    const float* wq    = (const float*)d_in[1];
    const float* wk    = (const float*)d_in[2];
    const float* bk    = (const float*)d_in[3];
    const float* wv    = (const float*)d_in[4];
    const float* bv    = (const float*)d_in[5];
    const float* rel_x = (const float*)d_in[6];
    const float* rel_y = (const float*)d_in[7];
    float* out = (float*)d_out;

    qkv_kernel<<<784, 256>>>(x, wq, wk, bk, wv, bv);

    dim3 grid(H/TH, COUT, B);   // (7, 64, 4) = 1792 blocks
    attn_kernel<<<grid, 224>>>(rel_x, rel_y, bk, bv, out);
}